// round 15
// baseline (speedup 1.0000x reference)
#include <cuda_runtime.h>
#include <cuda_fp16.h>
#include <cstdint>

#define NN     20000
#define NEIGH  12
#define EE     (NN*NEIGH)
#define HD     64
#define INB    480
#define INBP   512          // padded K for bond
#define INA    2880
#define NCRYS  20

// ---------------- scratch ----------------------------------------------------
__device__ __align__(256) __half g_Xa[(size_t)NN * INA];
__device__ __align__(256) __half g_Xb[(size_t)NN * INBP];
__device__ __align__(256) __half g_Wta[256 * INA];
__device__ __align__(256) __half g_Wtb[256 * INBP];
__device__ __align__(256) __half g_Wt2a[256 * HD];
__device__ __align__(256) __half g_Wt2b[256 * HD];
__device__ float g_Ha[(size_t)NN * 256];
__device__ float g_Hb[(size_t)NN * 256];
__device__ float g_bf[NN * HD];
__device__ float g_af[NN * HD];
__device__ __align__(256) __half g_bfx[NN * HD];
__device__ __align__(256) __half g_afx[NN * HD];
__device__ int   g_cnt[NN * 3];
__device__ int   g_deg[NN];
__device__ int   g_off[NN + 1];
__device__ int   g_pos[NN];
__device__ int   g_rev[EE];
__device__ float g_pool[NCRYS * 128];

// ---------------- helpers ------------------------------------------------------
__device__ __forceinline__ uint32_t smem_u32(const void* p) {
    uint32_t a;
    asm("{ .reg .u64 t; cvta.to.shared.u64 t, %1; cvt.u32.u64 %0, t; }"
        : "=r"(a) : "l"(p));
    return a;
}

__device__ __forceinline__ void cp16(uint32_t dst, const void* src, int sz) {
    asm volatile("cp.async.cg.shared.global [%0], [%1], 16, %2;"
                 :: "r"(dst), "l"(src), "r"(sz));
}

__device__ __forceinline__ void ldmx4(uint32_t* r, uint32_t addr) {
    asm volatile("ldmatrix.sync.aligned.m8n8.x4.shared.b16 {%0,%1,%2,%3}, [%4];"
                 : "=r"(r[0]), "=r"(r[1]), "=r"(r[2]), "=r"(r[3]) : "r"(addr));
}

__device__ __forceinline__ void mma16816(float* c, const uint32_t* a, const uint32_t* b) {
    asm volatile(
        "mma.sync.aligned.m16n8k16.row.col.f32.f16.f16.f32 "
        "{%0,%1,%2,%3}, {%4,%5,%6,%7}, {%8,%9}, {%0,%1,%2,%3};"
        : "+f"(c[0]), "+f"(c[1]), "+f"(c[2]), "+f"(c[3])
        : "r"(a[0]), "r"(a[1]), "r"(a[2]), "r"(a[3]), "r"(b[0]), "r"(b[1]));
}

// ---------------- standalone Gaussian expansions --------------------------------
__global__ void expand_bond(const float* __restrict__ bond) {
    int idx = blockIdx.x * blockDim.x + threadIdx.x;
    if (idx >= NN * NEIGH) return;
    int v = idx / NEIGH, j = idx - v * NEIGH;
    float d = bond[idx];
    uint32_t hw[20];
#pragma unroll
    for (int i = 0; i < 20; i++) {
        uint32_t h2 = 0;
#pragma unroll
        for (int q = 0; q < 2; q++) {
            float t = d - (float)(2 * i + q) * (8.0f / 39.0f);
            float x = __expf(-t * t * 25.0f);
            h2 |= (uint32_t)__half_as_ushort(__float2half_rn(x)) << (16 * q);
        }
        hw[i] = h2;
    }
    uint4* ph = (uint4*)(g_Xb + (size_t)v * INBP + j * 40);
#pragma unroll
    for (int u = 0; u < 5; u++)
        ph[u] = make_uint4(hw[4*u], hw[4*u+1], hw[4*u+2], hw[4*u+3]);
    if (j == 0) {   // zero the pad columns 480..511
        uint4* pz = (uint4*)(g_Xb + (size_t)v * INBP + INB);
#pragma unroll
        for (int u = 0; u < 4; u++) pz[u] = make_uint4(0, 0, 0, 0);
    }
}

__global__ void expand_angle(const float* __restrict__ ang) {
    int idx = blockIdx.x * blockDim.x + threadIdx.x;
    if (idx >= NN * 72) return;
    int v = idx / 72, p = idx - v * 72;
    float d0 = ang[(size_t)v * 144 + 2 * p];
    float d1 = ang[(size_t)v * 144 + 2 * p + 1];
    uint32_t hw[20];
#pragma unroll
    for (int half = 0; half < 2; half++) {
        float d = half ? d1 : d0;
#pragma unroll
        for (int i = 0; i < 10; i++) {
            uint32_t h2 = 0;
#pragma unroll
            for (int q = 0; q < 2; q++) {
                float t = d - (-1.0f + (float)(2 * i + q) * (2.0f / 19.0f));
                float x = __expf(-t * t * 100.0f);
                h2 |= (uint32_t)__half_as_ushort(__float2half_rn(x)) << (16 * q);
            }
            hw[half * 10 + i] = h2;
        }
    }
    uint4* ph = (uint4*)(g_Xa + (size_t)v * INA + p * 40);
#pragma unroll
    for (int u = 0; u < 5; u++)
        ph[u] = make_uint4(hw[4*u], hw[4*u+1], hw[4*u+2], hw[4*u+3]);
}

// ---------------- GEMM: H[M,256] = X @ W^T (fp16, K-chunk 64) -------------------
// CTA 128x128, 256 thr, 2 CTAs/SM. Rows 144B (128 data + 16 pad, conflict-free).
// 3-stage cp.async pipeline, one __syncthreads per 64-K chunk.
#define ROWB  144
#define SM_A  0
#define SM_B  18432
#define STAGE 36864
#define SMEM_GEMM (3 * STAGE)

__device__ __forceinline__ void load_chunk(uint32_t sb, int c,
                                           const __half* A, const __half* B,
                                           int K, int m0, int n0, int tid) {
#pragma unroll
    for (int q = 0; q < 4; q++) {
        int j = tid + q * 256;                 // 0..1023
        int row = j >> 3, cc = j & 7;
        uint32_t doff = (uint32_t)(row * ROWB + cc * 16);
        int gm = m0 + row;
        int gmc = gm < NN ? gm : 0;
        int sz = gm < NN ? 16 : 0;
        cp16(sb + SM_A + doff, A + (size_t)gmc * K + c * 64 + cc * 8, sz);
        cp16(sb + SM_B + doff, B + (size_t)(n0 + row) * K + c * 64 + cc * 8, 16);
    }
    asm volatile("cp.async.commit_group;" ::: "memory");
}

__global__ __launch_bounds__(256, 2)
void gemm_mma(const __half* __restrict__ A,
              const __half* __restrict__ B,
              float* __restrict__ H,
              int K) {
    extern __shared__ char smem[];
    uint32_t sbase = smem_u32(smem);
    int tid = threadIdx.x;
    int w = tid >> 5, l = tid & 31;
    int m0 = blockIdx.x * 128;
    int n0 = blockIdx.y * 128;
    int warp_m = (w >> 1) * 32;
    int warp_n = (w & 1) * 64;
    int nchunks = K >> 6;

    float acc[2][8][4];
#pragma unroll
    for (int i = 0; i < 2; i++)
#pragma unroll
        for (int j = 0; j < 8; j++)
#pragma unroll
            for (int q = 0; q < 4; q++) acc[i][j][q] = 0.f;

    uint32_t a_off[2];
#pragma unroll
    for (int mt = 0; mt < 2; mt++)
        a_off[mt] = (uint32_t)((warp_m + mt * 16 + (l & 15)) * ROWB + ((l >> 4) * 16));
    uint32_t b_base = (uint32_t)((warp_n + (l & 7) + ((l >> 4) << 3)) * ROWB +
                                 (((l >> 3) & 1) * 16));

    load_chunk(sbase, 0, A, B, K, m0, n0, tid);
    if (nchunks > 1) load_chunk(sbase + STAGE, 1, A, B, K, m0, n0, tid);

    int st = 0;
    for (int c = 0; c < nchunks; c++) {
        if (c == nchunks - 1)
            asm volatile("cp.async.wait_group 0;" ::: "memory");
        else
            asm volatile("cp.async.wait_group 1;" ::: "memory");
        __syncthreads();

        uint32_t sb = sbase + (uint32_t)(st * STAGE);
#pragma unroll
        for (int s = 0; s < 4; s++) {
            uint32_t af[2][4];
#pragma unroll
            for (int mt = 0; mt < 2; mt++)
                ldmx4(af[mt], sb + SM_A + a_off[mt] + s * 32);
#pragma unroll
            for (int p = 0; p < 4; p++) {
                uint32_t rb[4];
                ldmx4(rb, sb + SM_B + b_base + (uint32_t)(p * 16 * ROWB) + s * 32);
#pragma unroll
                for (int mt = 0; mt < 2; mt++) {
                    mma16816(acc[mt][2 * p],     af[mt], rb);
                    mma16816(acc[mt][2 * p + 1], af[mt], rb + 2);
                }
            }
        }
        if (c + 2 < nchunks) {
            int st2 = (st + 2) % 3;
            load_chunk(sbase + (uint32_t)(st2 * STAGE), c + 2, A, B, K, m0, n0, tid);
        }
        st = (st + 1) % 3;
    }

#pragma unroll
    for (int mt = 0; mt < 2; mt++) {
        int m1 = m0 + warp_m + mt * 16 + (l >> 2);
        int m2 = m1 + 8;
#pragma unroll
        for (int nt = 0; nt < 8; nt++) {
            int nc = n0 + warp_n + nt * 8 + 2 * (l & 3);
            if (m1 < NN)
                *(float2*)(H + (size_t)m1 * 256 + nc) =
                    make_float2(acc[mt][nt][0], acc[mt][nt][1]);
            if (m2 < NN)
                *(float2*)(H + (size_t)m2 * 256 + nc) =
                    make_float2(acc[mt][nt][2], acc[mt][nt][3]);
        }
    }
}

// ---------------- weight transpose + fp16 convert (padded dest) ----------------
__global__ void prep_wT(const float* __restrict__ Wroot,
                        const float* __restrict__ Wrel,
                        __half* __restrict__ Wt, int K, int Kp) {
    __shared__ float sm[32][65];
    int tid = threadIdx.x;
    int k0 = blockIdx.x * 32;
    int cb = blockIdx.y;
#pragma unroll
    for (int i = 0; i < 8; i++) {
        int e = tid + i * 256;
        int k = e >> 6, h = e & 63;
        float wv = 0.f;
        if (k0 + k < K)
            wv = (cb == 0) ? Wroot[(size_t)(k0 + k) * 64 + h]
                           : Wrel[(size_t)(cb - 1) * K * 64 + (size_t)(k0 + k) * 64 + h];
        sm[k][h] = wv;
    }
    __syncthreads();
#pragma unroll
    for (int i = 0; i < 8; i++) {
        int e = tid + i * 256;
        int h = e >> 5, kk = e & 31;
        Wt[(size_t)(cb * 64 + h) * Kp + k0 + kk] = __float2half_rn(sm[kk][h]);
    }
}

// ---------------- graph preprocessing ------------------------------------------
__global__ void zero_kernel() {
    int i = blockIdx.x * blockDim.x + threadIdx.x;
    if (i < NN * 3) g_cnt[i] = 0;
    if (i < NN) g_deg[i] = 0;
    if (i < NCRYS * 128) g_pool[i] = 0.f;
}

__global__ void count_kernel(const int* __restrict__ nbr,
                             const int* __restrict__ species) {
    int e = blockIdx.x * blockDim.x + threadIdx.x;
    if (e >= EE) return;
    int src = e / NEIGH;
    int dst = nbr[e];
    int et = species[src] + species[dst];
    atomicAdd(&g_cnt[dst * 3 + et], 1);
    atomicAdd(&g_deg[dst], 1);
}

__global__ void scan_kernel() {
    __shared__ int ps[1024];
    int t = threadIdx.x;
    int base = t * 20;
    int local[20];
    int s = 0;
#pragma unroll
    for (int i = 0; i < 20; i++) {
        int idx = base + i;
        int d = (idx < NN) ? g_deg[idx] : 0;
        local[i] = s;
        s += d;
    }
    ps[t] = s;
    __syncthreads();
    for (int off = 1; off < 1024; off <<= 1) {
        int v = (t >= off) ? ps[t - off] : 0;
        __syncthreads();
        ps[t] += v;
        __syncthreads();
    }
    int pre = (t > 0) ? ps[t - 1] : 0;
#pragma unroll
    for (int i = 0; i < 20; i++) {
        int idx = base + i;
        if (idx < NN) {
            g_off[idx] = pre + local[i];
            g_pos[idx] = pre + local[i];
        }
    }
    if (t == 1023) g_off[NN] = ps[1023];
}

__global__ void fill_kernel(const int* __restrict__ nbr,
                            const int* __restrict__ species) {
    int e = blockIdx.x * blockDim.x + threadIdx.x;
    if (e >= EE) return;
    int src = e / NEIGH;
    int dst = nbr[e];
    int et = species[src] + species[dst];
    int p = atomicAdd(&g_pos[dst], 1);
    g_rev[p] = (src << 2) | et;
}

// ---------------- gather aggregation (4-way split edge loop) --------------------
// 256 threads: 1 dst x 4 edge-slots x 64 h. Serial chain ~3 L2 loads per slot.
template<int OUT>
__global__ void gather_kernel(const float* __restrict__ H,
                              const float* __restrict__ bias,
                              __half* __restrict__ ox,
                              float* __restrict__ of) {
    __shared__ float part[192];
    int tid = threadIdx.x;
    int es = tid >> 6;
    int h = tid & 63;
    int dst = blockIdx.x;
    int c0 = g_cnt[dst * 3 + 0], c1 = g_cnt[dst * 3 + 1], c2 = g_cnt[dst * 3 + 2];
    float inv0 = 1.0f / (float)(c0 > 0 ? c0 : 1);
    float inv1 = 1.0f / (float)(c1 > 0 ? c1 : 1);
    float inv2 = 1.0f / (float)(c2 > 0 ? c2 : 1);
    int b0 = g_off[dst], b1 = g_off[dst + 1];
    float v = 0.f;
    for (int p = b0 + es; p < b1; p += 4) {
        int pk = g_rev[p];
        int src = pk >> 2, et = pk & 3;
        float ic = (et == 0) ? inv0 : ((et == 1) ? inv1 : inv2);
        v += H[(size_t)src * 256 + (et + 1) * 64 + h] * ic;
    }
    if (es) part[(es - 1) * 64 + h] = v;
    __syncthreads();
    if (es == 0) {
        v += part[h] + part[64 + h] + part[128 + h];
        v += H[(size_t)dst * 256 + h] + bias[h];
        v = v > 0.f ? v : 0.f;
        if (OUT == 0) ox[dst * 64 + h] = __float2half_rn(v);
        else          of[dst * 64 + h] = v;
    }
}

// ---------------- pooling + FC ---------------------------------------------------
#define POOL_NODES 160
__global__ void pool_kernel(const int* __restrict__ crys) {
    __shared__ int starts[NCRYS];
    int t = threadIdx.x;
    if (t < NCRYS) starts[t] = crys[t * 2];
    __syncthreads();
    int v0 = blockIdx.x * POOL_NODES;
    int v1 = v0 + POOL_NODES;
    if (v1 > NN) v1 = NN;
    const float* srcbuf = (t < 64) ? g_bf : g_af;
    int h = t & 63;
    float sum = 0.f;
    int cur = -2;
    for (int v = v0; v < v1; v++) {
        int c = 0;
#pragma unroll
        for (int k = 1; k < NCRYS; k++)
            if (starts[k] <= v) c = k;
        if (c != cur) {
            if (cur >= 0) atomicAdd(&g_pool[cur * 128 + t], sum);
            sum = 0.f;
            cur = c;
        }
        sum += srcbuf[v * 64 + h];
    }
    if (cur >= 0) atomicAdd(&g_pool[cur * 128 + t], sum);
}

__global__ void fc_kernel(const int* __restrict__ crys,
                          const float* __restrict__ W,
                          const float* __restrict__ b,
                          float* __restrict__ out) {
    int t = threadIdx.x;
    if (t >= NCRYS * 2) return;
    int c = t >> 1, o = t & 1;
    float cnt = (float)(crys[c * 2 + 1] - crys[c * 2]);
    float inv = 1.0f / cnt;
    float s = 0.f;
    for (int h = 0; h < 128; h++)
        s += g_pool[c * 128 + h] * inv * W[h * 2 + o];
    out[t] = s + b[o];
}

// ---------------- launch ----------------------------------------------------------
extern "C" void kernel_launch(void* const* d_in, const int* in_sizes, int n_in,
                              void* d_out, int out_size) {
    const float* bond     = (const float*)d_in[0];
    const float* angle    = (const float*)d_in[1];
    const int*   species  = (const int*)d_in[2];
    const int*   nbr      = (const int*)d_in[3];
    const int*   crys     = (const int*)d_in[4];
    const float* W1b_rel  = (const float*)d_in[5];
    const float* W1b_root = (const float*)d_in[6];
    const float* b1b      = (const float*)d_in[7];
    const float* W1a_rel  = (const float*)d_in[8];
    const float* W1a_root = (const float*)d_in[9];
    const float* b1a      = (const float*)d_in[10];
    const float* W2b_rel  = (const float*)d_in[11];
    const float* W2b_root = (const float*)d_in[12];
    const float* b2b      = (const float*)d_in[13];
    const float* W2a_rel  = (const float*)d_in[14];
    const float* W2a_root = (const float*)d_in[15];
    const float* b2a      = (const float*)d_in[16];
    const float* fcW      = (const float*)d_in[17];
    const float* fcb      = (const float*)d_in[18];
    float* out = (float*)d_out;

    static cudaStream_t sB = nullptr, sC = nullptr, sD = nullptr;
    static cudaEvent_t evFork, evGraph, evPrepA, evPrep2A, evJoin;
    if (!sB) {
        cudaStreamCreateWithFlags(&sB, cudaStreamNonBlocking);
        cudaStreamCreateWithFlags(&sC, cudaStreamNonBlocking);
        cudaStreamCreateWithFlags(&sD, cudaStreamNonBlocking);
        cudaEventCreateWithFlags(&evFork,   cudaEventDisableTiming);
        cudaEventCreateWithFlags(&evGraph,  cudaEventDisableTiming);
        cudaEventCreateWithFlags(&evPrepA,  cudaEventDisableTiming);
        cudaEventCreateWithFlags(&evPrep2A, cudaEventDisableTiming);
        cudaEventCreateWithFlags(&evJoin,   cudaEventDisableTiming);
    }

    cudaFuncSetAttribute(gemm_mma, cudaFuncAttributeMaxDynamicSharedMemorySize, SMEM_GEMM);

    __half *Xa, *Xb, *Wta, *Wtb, *Wt2a, *Wt2b, *bfx, *afx;
    float *Ha, *Hb, *bfp, *afp;
    cudaGetSymbolAddress((void**)&Xa,  g_Xa);
    cudaGetSymbolAddress((void**)&Xb,  g_Xb);
    cudaGetSymbolAddress((void**)&Wta, g_Wta);
    cudaGetSymbolAddress((void**)&Wtb, g_Wtb);
    cudaGetSymbolAddress((void**)&Wt2a, g_Wt2a);
    cudaGetSymbolAddress((void**)&Wt2b, g_Wt2b);
    cudaGetSymbolAddress((void**)&Ha,  g_Ha);
    cudaGetSymbolAddress((void**)&Hb,  g_Hb);
    cudaGetSymbolAddress((void**)&bfx, g_bfx);
    cudaGetSymbolAddress((void**)&afx, g_afx);
    cudaGetSymbolAddress((void**)&bfp, g_bf);
    cudaGetSymbolAddress((void**)&afp, g_af);

    const int T = 256;
    dim3 ggrid((NN + 127) / 128, 2);

    // ---- default: zero, then fork ----
    zero_kernel<<<(NN * 3 + T - 1) / T, T>>>();
    cudaEventRecord(evFork, 0);
    cudaStreamWaitEvent(sB, evFork, 0);
    cudaStreamWaitEvent(sC, evFork, 0);
    cudaStreamWaitEvent(sD, evFork, 0);

    // ---- sC: graph preprocessing ----
    count_kernel<<<(EE + T - 1) / T, T, 0, sC>>>(nbr, species);
    scan_kernel<<<1, 1024, 0, sC>>>();
    fill_kernel<<<(EE + T - 1) / T, T, 0, sC>>>(nbr, species);
    cudaEventRecord(evGraph, sC);

    // ---- sD: angle weight preps ----
    prep_wT<<<dim3(INA / 32, 4), 256, 0, sD>>>(W1a_root, W1a_rel, Wta, INA, INA);
    cudaEventRecord(evPrepA, sD);
    prep_wT<<<dim3(HD / 32, 4), 256, 0, sD>>>(W2a_root, W2a_rel, Wt2a, HD, HD);
    cudaEventRecord(evPrep2A, sD);

    // ---- sB: bond chain (K padded to 512) ----
    expand_bond<<<(NN * NEIGH + T - 1) / T, T, 0, sB>>>(bond);
    prep_wT<<<dim3(INBP / 32, 4), 256, 0, sB>>>(W1b_root, W1b_rel, Wtb, INB, INBP);
    gemm_mma<<<ggrid, 256, SMEM_GEMM, sB>>>(Xb, Wtb, Hb, INBP);
    cudaStreamWaitEvent(sB, evGraph, 0);
    gather_kernel<0><<<NN, 256, 0, sB>>>(Hb, b1b, bfx, nullptr);
    prep_wT<<<dim3(HD / 32, 4), 256, 0, sB>>>(W2b_root, W2b_rel, Wt2b, HD, HD);
    gemm_mma<<<ggrid, 256, SMEM_GEMM, sB>>>(bfx, Wt2b, Hb, HD);
    gather_kernel<1><<<NN, 256, 0, sB>>>(Hb, b2b, nullptr, bfp);
    cudaEventRecord(evJoin, sB);

    // ---- default: angle chain (critical path) ----
    expand_angle<<<(NN * 72 + T - 1) / T, T>>>(angle);
    cudaStreamWaitEvent(0, evPrepA, 0);
    gemm_mma<<<ggrid, 256, SMEM_GEMM>>>(Xa, Wta, Ha, INA);
    cudaStreamWaitEvent(0, evGraph, 0);
    gather_kernel<0><<<NN, 256>>>(Ha, b1a, afx, nullptr);
    cudaStreamWaitEvent(0, evPrep2A, 0);
    gemm_mma<<<ggrid, 256, SMEM_GEMM>>>(afx, Wt2a, Ha, HD);
    gather_kernel<1><<<NN, 256>>>(Ha, b2a, nullptr, afp);

    // ---- join + pooling + FC ----
    cudaStreamWaitEvent(0, evJoin, 0);
    pool_kernel<<<(NN + POOL_NODES - 1) / POOL_NODES, 128>>>(crys);
    fc_kernel<<<1, 64>>>(crys, fcW, fcb, out);
}

// round 16
// speedup vs baseline: 1.0075x; 1.0075x over previous
#include <cuda_runtime.h>
#include <cuda_fp16.h>
#include <cstdint>

#define NN     20000
#define NEIGH  12
#define EE     (NN*NEIGH)
#define HD     64
#define INB    480
#define INA    2880
#define NCRYS  20

// ---------------- scratch ----------------------------------------------------
__device__ __align__(256) __half g_Xa[(size_t)NN * INA];
__device__ __align__(256) __half g_Xb[(size_t)NN * INB];
__device__ __align__(256) __half g_Wta[256 * INA];
__device__ __align__(256) __half g_Wtb[256 * INB];
__device__ __align__(256) __half g_Wt2a[256 * HD];
__device__ __align__(256) __half g_Wt2b[256 * HD];
__device__ float g_Ha[(size_t)NN * 256];
__device__ float g_Hb[(size_t)NN * 256];
__device__ float g_bf[NN * HD];
__device__ float g_af[NN * HD];
__device__ __align__(256) __half g_bfx[NN * HD];
__device__ __align__(256) __half g_afx[NN * HD];
__device__ int   g_cnt[NN * 3];
__device__ int   g_deg[NN];
__device__ int   g_off[NN + 1];
__device__ int   g_pos[NN];
__device__ int   g_rev[EE];
__device__ float g_pool[NCRYS * 128];

// ---------------- helpers ------------------------------------------------------
__device__ __forceinline__ uint32_t smem_u32(const void* p) {
    uint32_t a;
    asm("{ .reg .u64 t; cvta.to.shared.u64 t, %1; cvt.u32.u64 %0, t; }"
        : "=r"(a) : "l"(p));
    return a;
}

__device__ __forceinline__ void cp16(uint32_t dst, const void* src, int sz) {
    asm volatile("cp.async.cg.shared.global [%0], [%1], 16, %2;"
                 :: "r"(dst), "l"(src), "r"(sz));
}

__device__ __forceinline__ void ldmx4(uint32_t* r, uint32_t addr) {
    asm volatile("ldmatrix.sync.aligned.m8n8.x4.shared.b16 {%0,%1,%2,%3}, [%4];"
                 : "=r"(r[0]), "=r"(r[1]), "=r"(r[2]), "=r"(r[3]) : "r"(addr));
}

__device__ __forceinline__ void mma16816(float* c, const uint32_t* a, const uint32_t* b) {
    asm volatile(
        "mma.sync.aligned.m16n8k16.row.col.f32.f16.f16.f32 "
        "{%0,%1,%2,%3}, {%4,%5,%6,%7}, {%8,%9}, {%0,%1,%2,%3};"
        : "+f"(c[0]), "+f"(c[1]), "+f"(c[2]), "+f"(c[3])
        : "r"(a[0]), "r"(a[1]), "r"(a[2]), "r"(a[3]), "r"(b[0]), "r"(b[1]));
}

// ---------------- standalone Gaussian expansions --------------------------------
__global__ void expand_bond(const float* __restrict__ bond) {
    int idx = blockIdx.x * blockDim.x + threadIdx.x;
    if (idx >= NN * NEIGH) return;
    int v = idx / NEIGH, j = idx - v * NEIGH;
    float d = bond[idx];
    uint32_t hw[20];
#pragma unroll
    for (int i = 0; i < 20; i++) {
        uint32_t h2 = 0;
#pragma unroll
        for (int q = 0; q < 2; q++) {
            float t = d - (float)(2 * i + q) * (8.0f / 39.0f);
            float x = __expf(-t * t * 25.0f);
            h2 |= (uint32_t)__half_as_ushort(__float2half_rn(x)) << (16 * q);
        }
        hw[i] = h2;
    }
    uint4* ph = (uint4*)(g_Xb + (size_t)v * INB + j * 40);
#pragma unroll
    for (int u = 0; u < 5; u++)
        ph[u] = make_uint4(hw[4*u], hw[4*u+1], hw[4*u+2], hw[4*u+3]);
}

__global__ void expand_angle(const float* __restrict__ ang) {
    int idx = blockIdx.x * blockDim.x + threadIdx.x;
    if (idx >= NN * 72) return;
    int v = idx / 72, p = idx - v * 72;
    float d0 = ang[(size_t)v * 144 + 2 * p];
    float d1 = ang[(size_t)v * 144 + 2 * p + 1];
    uint32_t hw[20];
#pragma unroll
    for (int half = 0; half < 2; half++) {
        float d = half ? d1 : d0;
#pragma unroll
        for (int i = 0; i < 10; i++) {
            uint32_t h2 = 0;
#pragma unroll
            for (int q = 0; q < 2; q++) {
                float t = d - (-1.0f + (float)(2 * i + q) * (2.0f / 19.0f));
                float x = __expf(-t * t * 100.0f);
                h2 |= (uint32_t)__half_as_ushort(__float2half_rn(x)) << (16 * q);
            }
            hw[half * 10 + i] = h2;
        }
    }
    uint4* ph = (uint4*)(g_Xa + (size_t)v * INA + p * 40);
#pragma unroll
    for (int u = 0; u < 5; u++)
        ph[u] = make_uint4(hw[4*u], hw[4*u+1], hw[4*u+2], hw[4*u+3]);
}

// ---------------- GEMM: H[M,256] = X @ W^T (fp16, 128x64 tile, 3 CTAs/SM) ------
// CTA 128(M) x 64(N), 256 thr, grid (157,4). K-chunk 32, 4-stage cp.async.
// smem rows 80B-padded (conflict-free ldmatrix).
#define SM_A  0
#define SM_B  10240
#define STAGE 15360
#define SMEM_GEMM (4 * STAGE)

__device__ __forceinline__ void load_chunk(uint32_t sb, int c,
                                           const __half* A, const __half* B,
                                           int K, int m0, int n0, int tid) {
#pragma unroll
    for (int q = 0; q < 2; q++) {
        int j = tid + q * 256;
        int row = j >> 2, cc = j & 3;
        uint32_t doff = (uint32_t)(row * 80 + cc * 16);
        int gm = m0 + row;
        int gmc = gm < NN ? gm : 0;
        int sz = gm < NN ? 16 : 0;
        cp16(sb + SM_A + doff, A + (size_t)gmc * K + c * 32 + cc * 8, sz);
    }
    {
        int row = tid >> 2, cc = tid & 3;
        uint32_t doff = (uint32_t)(row * 80 + cc * 16);
        cp16(sb + SM_B + doff, B + (size_t)(n0 + row) * K + c * 32 + cc * 8, 16);
    }
    asm volatile("cp.async.commit_group;" ::: "memory");
}

__global__ __launch_bounds__(256, 3)
void gemm_mma(const __half* __restrict__ A,
              const __half* __restrict__ B,
              float* __restrict__ H,
              int K) {
    extern __shared__ char smem[];
    uint32_t sbase = smem_u32(smem);
    int tid = threadIdx.x;
    int w = tid >> 5, l = tid & 31;
    int m0 = blockIdx.x * 128;
    int n0 = blockIdx.y * 64;
    int warp_m = (w >> 1) * 32;
    int warp_n = (w & 1) * 32;
    int nchunks = K >> 5;

    float acc[2][4][4];
#pragma unroll
    for (int i = 0; i < 2; i++)
#pragma unroll
        for (int j = 0; j < 4; j++)
#pragma unroll
            for (int q = 0; q < 4; q++) acc[i][j][q] = 0.f;

    uint32_t a_off[2];
#pragma unroll
    for (int mt = 0; mt < 2; mt++)
        a_off[mt] = (uint32_t)((warp_m + mt * 16 + (l & 15)) * 80 + ((l >> 4) * 16));
    uint32_t b_base = (uint32_t)((warp_n + (l & 7) + ((l >> 4) << 3)) * 80 +
                                 (((l >> 3) & 1) * 16));

    load_chunk(sbase, 0, A, B, K, m0, n0, tid);
    if (nchunks > 1) load_chunk(sbase + STAGE, 1, A, B, K, m0, n0, tid);
    if (nchunks > 2) load_chunk(sbase + 2 * STAGE, 2, A, B, K, m0, n0, tid);

    int st = 0;
    for (int c = 0; c < nchunks; c++) {
        int rem = nchunks - 1 - c;
        if (rem >= 2)      asm volatile("cp.async.wait_group 2;" ::: "memory");
        else if (rem == 1) asm volatile("cp.async.wait_group 1;" ::: "memory");
        else               asm volatile("cp.async.wait_group 0;" ::: "memory");
        __syncthreads();

        uint32_t sb = sbase + (uint32_t)(st * STAGE);
#pragma unroll
        for (int s = 0; s < 2; s++) {
            uint32_t af[2][4];
#pragma unroll
            for (int mt = 0; mt < 2; mt++)
                ldmx4(af[mt], sb + SM_A + a_off[mt] + s * 32);
#pragma unroll
            for (int p = 0; p < 2; p++) {
                uint32_t rb[4];
                ldmx4(rb, sb + SM_B + b_base + (uint32_t)(p * 1280) + s * 32);
#pragma unroll
                for (int mt = 0; mt < 2; mt++) {
                    mma16816(acc[mt][2 * p],     af[mt], rb);
                    mma16816(acc[mt][2 * p + 1], af[mt], rb + 2);
                }
            }
        }
        if (c + 3 < nchunks) {
            int st3 = (st + 3) & 3;
            load_chunk(sbase + (uint32_t)(st3 * STAGE), c + 3, A, B, K, m0, n0, tid);
        }
        st = (st + 1) & 3;
    }

#pragma unroll
    for (int mt = 0; mt < 2; mt++) {
        int m1 = m0 + warp_m + mt * 16 + (l >> 2);
        int m2 = m1 + 8;
#pragma unroll
        for (int nt = 0; nt < 4; nt++) {
            int nc = n0 + warp_n + nt * 8 + 2 * (l & 3);
            if (m1 < NN)
                *(float2*)(H + (size_t)m1 * 256 + nc) =
                    make_float2(acc[mt][nt][0], acc[mt][nt][1]);
            if (m2 < NN)
                *(float2*)(H + (size_t)m2 * 256 + nc) =
                    make_float2(acc[mt][nt][2], acc[mt][nt][3]);
        }
    }
}

// ---------------- weight transpose + fp16 convert ------------------------------
__global__ void prep_wT(const float* __restrict__ Wroot,
                        const float* __restrict__ Wrel,
                        __half* __restrict__ Wt, int K) {
    __shared__ float sm[32][65];
    int tid = threadIdx.x;
    int k0 = blockIdx.x * 32;
    int cb = blockIdx.y;
#pragma unroll
    for (int i = 0; i < 8; i++) {
        int e = tid + i * 256;
        int k = e >> 6, h = e & 63;
        float wv = (cb == 0) ? Wroot[(size_t)(k0 + k) * 64 + h]
                             : Wrel[(size_t)(cb - 1) * K * 64 + (size_t)(k0 + k) * 64 + h];
        sm[k][h] = wv;
    }
    __syncthreads();
#pragma unroll
    for (int i = 0; i < 8; i++) {
        int e = tid + i * 256;
        int h = e >> 5, kk = e & 31;
        Wt[(size_t)(cb * 64 + h) * K + k0 + kk] = __float2half_rn(sm[kk][h]);
    }
}

// ---------------- graph preprocessing ------------------------------------------
__global__ void zero_kernel() {
    int i = blockIdx.x * blockDim.x + threadIdx.x;
    if (i < NN * 3) g_cnt[i] = 0;
    if (i < NN) g_deg[i] = 0;
    if (i < NCRYS * 128) g_pool[i] = 0.f;
}

__global__ void count_kernel(const int* __restrict__ nbr,
                             const int* __restrict__ species) {
    int e = blockIdx.x * blockDim.x + threadIdx.x;
    if (e >= EE) return;
    int src = e / NEIGH;
    int dst = nbr[e];
    int et = species[src] + species[dst];
    atomicAdd(&g_cnt[dst * 3 + et], 1);
    atomicAdd(&g_deg[dst], 1);
}

__global__ void scan_kernel() {
    __shared__ int ps[1024];
    int t = threadIdx.x;
    int base = t * 20;
    int local[20];
    int s = 0;
#pragma unroll
    for (int i = 0; i < 20; i++) {
        int idx = base + i;
        int d = (idx < NN) ? g_deg[idx] : 0;
        local[i] = s;
        s += d;
    }
    ps[t] = s;
    __syncthreads();
    for (int off = 1; off < 1024; off <<= 1) {
        int v = (t >= off) ? ps[t - off] : 0;
        __syncthreads();
        ps[t] += v;
        __syncthreads();
    }
    int pre = (t > 0) ? ps[t - 1] : 0;
#pragma unroll
    for (int i = 0; i < 20; i++) {
        int idx = base + i;
        if (idx < NN) {
            g_off[idx] = pre + local[i];
            g_pos[idx] = pre + local[i];
        }
    }
    if (t == 1023) g_off[NN] = ps[1023];
}

__global__ void fill_kernel(const int* __restrict__ nbr,
                            const int* __restrict__ species) {
    int e = blockIdx.x * blockDim.x + threadIdx.x;
    if (e >= EE) return;
    int src = e / NEIGH;
    int dst = nbr[e];
    int et = species[src] + species[dst];
    int p = atomicAdd(&g_pos[dst], 1);
    g_rev[p] = (src << 2) | et;
}

// ---------------- gather aggregation (2-way split edge loop) --------------------
template<int OUT>
__global__ void gather_kernel(const float* __restrict__ H,
                              const float* __restrict__ bias,
                              __half* __restrict__ ox,
                              float* __restrict__ of) {
    __shared__ float part[128];
    int tid = threadIdx.x;
    int ld = tid >> 7;
    int es = (tid >> 6) & 1;
    int h = tid & 63;
    int dst = blockIdx.x * 2 + ld;
    float v = 0.f;
    if (dst < NN) {
        int c0 = g_cnt[dst * 3 + 0], c1 = g_cnt[dst * 3 + 1], c2 = g_cnt[dst * 3 + 2];
        float inv0 = 1.0f / (float)(c0 > 0 ? c0 : 1);
        float inv1 = 1.0f / (float)(c1 > 0 ? c1 : 1);
        float inv2 = 1.0f / (float)(c2 > 0 ? c2 : 1);
        int b0 = g_off[dst], b1 = g_off[dst + 1];
        for (int p = b0 + es; p < b1; p += 2) {
            int pk = g_rev[p];
            int src = pk >> 2, et = pk & 3;
            float ic = (et == 0) ? inv0 : ((et == 1) ? inv1 : inv2);
            v += H[(size_t)src * 256 + (et + 1) * 64 + h] * ic;
        }
    }
    if (es == 1) part[ld * 64 + h] = v;
    __syncthreads();
    if (es == 0 && dst < NN) {
        v += part[ld * 64 + h];
        v += H[(size_t)dst * 256 + h] + bias[h];
        v = v > 0.f ? v : 0.f;
        if (OUT == 0) ox[dst * 64 + h] = __float2half_rn(v);
        else          of[dst * 64 + h] = v;
    }
}

// ---------------- pooling + FC ---------------------------------------------------
#define POOL_NODES 160
__global__ void pool_kernel(const int* __restrict__ crys) {
    __shared__ int starts[NCRYS];
    int t = threadIdx.x;
    if (t < NCRYS) starts[t] = crys[t * 2];
    __syncthreads();
    int v0 = blockIdx.x * POOL_NODES;
    int v1 = v0 + POOL_NODES;
    if (v1 > NN) v1 = NN;
    const float* srcbuf = (t < 64) ? g_bf : g_af;
    int h = t & 63;
    float sum = 0.f;
    int cur = -2;
    for (int v = v0; v < v1; v++) {
        int c = 0;
#pragma unroll
        for (int k = 1; k < NCRYS; k++)
            if (starts[k] <= v) c = k;
        if (c != cur) {
            if (cur >= 0) atomicAdd(&g_pool[cur * 128 + t], sum);
            sum = 0.f;
            cur = c;
        }
        sum += srcbuf[v * 64 + h];
    }
    if (cur >= 0) atomicAdd(&g_pool[cur * 128 + t], sum);
}

__global__ void fc_kernel(const int* __restrict__ crys,
                          const float* __restrict__ W,
                          const float* __restrict__ b,
                          float* __restrict__ out) {
    int t = threadIdx.x;
    if (t >= NCRYS * 2) return;
    int c = t >> 1, o = t & 1;
    float cnt = (float)(crys[c * 2 + 1] - crys[c * 2]);
    float inv = 1.0f / cnt;
    float s = 0.f;
    for (int h = 0; h < 128; h++)
        s += g_pool[c * 128 + h] * inv * W[h * 2 + o];
    out[t] = s + b[o];
}

// ---------------- launch ----------------------------------------------------------
extern "C" void kernel_launch(void* const* d_in, const int* in_sizes, int n_in,
                              void* d_out, int out_size) {
    const float* bond     = (const float*)d_in[0];
    const float* angle    = (const float*)d_in[1];
    const int*   species  = (const int*)d_in[2];
    const int*   nbr      = (const int*)d_in[3];
    const int*   crys     = (const int*)d_in[4];
    const float* W1b_rel  = (const float*)d_in[5];
    const float* W1b_root = (const float*)d_in[6];
    const float* b1b      = (const float*)d_in[7];
    const float* W1a_rel  = (const float*)d_in[8];
    const float* W1a_root = (const float*)d_in[9];
    const float* b1a      = (const float*)d_in[10];
    const float* W2b_rel  = (const float*)d_in[11];
    const float* W2b_root = (const float*)d_in[12];
    const float* b2b      = (const float*)d_in[13];
    const float* W2a_rel  = (const float*)d_in[14];
    const float* W2a_root = (const float*)d_in[15];
    const float* b2a      = (const float*)d_in[16];
    const float* fcW      = (const float*)d_in[17];
    const float* fcb      = (const float*)d_in[18];
    float* out = (float*)d_out;

    static cudaStream_t sB = nullptr, sC = nullptr, sD = nullptr;
    static cudaEvent_t evFork, evGraph, evPrepA, evPrep2A, evJoin;
    if (!sB) {
        cudaStreamCreateWithFlags(&sB, cudaStreamNonBlocking);
        cudaStreamCreateWithFlags(&sC, cudaStreamNonBlocking);
        cudaStreamCreateWithFlags(&sD, cudaStreamNonBlocking);
        cudaEventCreateWithFlags(&evFork,   cudaEventDisableTiming);
        cudaEventCreateWithFlags(&evGraph,  cudaEventDisableTiming);
        cudaEventCreateWithFlags(&evPrepA,  cudaEventDisableTiming);
        cudaEventCreateWithFlags(&evPrep2A, cudaEventDisableTiming);
        cudaEventCreateWithFlags(&evJoin,   cudaEventDisableTiming);
    }

    cudaFuncSetAttribute(gemm_mma, cudaFuncAttributeMaxDynamicSharedMemorySize, SMEM_GEMM);

    __half *Xa, *Xb, *Wta, *Wtb, *Wt2a, *Wt2b, *bfx, *afx;
    float *Ha, *Hb, *bfp, *afp;
    cudaGetSymbolAddress((void**)&Xa,  g_Xa);
    cudaGetSymbolAddress((void**)&Xb,  g_Xb);
    cudaGetSymbolAddress((void**)&Wta, g_Wta);
    cudaGetSymbolAddress((void**)&Wtb, g_Wtb);
    cudaGetSymbolAddress((void**)&Wt2a, g_Wt2a);
    cudaGetSymbolAddress((void**)&Wt2b, g_Wt2b);
    cudaGetSymbolAddress((void**)&Ha,  g_Ha);
    cudaGetSymbolAddress((void**)&Hb,  g_Hb);
    cudaGetSymbolAddress((void**)&bfx, g_bfx);
    cudaGetSymbolAddress((void**)&afx, g_afx);
    cudaGetSymbolAddress((void**)&bfp, g_bf);
    cudaGetSymbolAddress((void**)&afp, g_af);

    const int T = 256;
    dim3 ggrid((NN + 127) / 128, 4);     // 128x64 tiles -> 3 CTAs/SM
    const int GGRID = (NN + 1) / 2;

    // ---- default: zero, then fork ----
    zero_kernel<<<(NN * 3 + T - 1) / T, T>>>();
    cudaEventRecord(evFork, 0);
    cudaStreamWaitEvent(sB, evFork, 0);
    cudaStreamWaitEvent(sC, evFork, 0);
    cudaStreamWaitEvent(sD, evFork, 0);

    // ---- sC: graph preprocessing ----
    count_kernel<<<(EE + T - 1) / T, T, 0, sC>>>(nbr, species);
    scan_kernel<<<1, 1024, 0, sC>>>();
    fill_kernel<<<(EE + T - 1) / T, T, 0, sC>>>(nbr, species);
    cudaEventRecord(evGraph, sC);

    // ---- sD: angle weight preps ----
    prep_wT<<<dim3(INA / 32, 4), 256, 0, sD>>>(W1a_root, W1a_rel, Wta, INA);
    cudaEventRecord(evPrepA, sD);
    prep_wT<<<dim3(HD / 32, 4), 256, 0, sD>>>(W2a_root, W2a_rel, Wt2a, HD);
    cudaEventRecord(evPrep2A, sD);

    // ---- sB: bond chain ----
    expand_bond<<<(NN * NEIGH + T - 1) / T, T, 0, sB>>>(bond);
    prep_wT<<<dim3(INB / 32, 4), 256, 0, sB>>>(W1b_root, W1b_rel, Wtb, INB);
    gemm_mma<<<ggrid, 256, SMEM_GEMM, sB>>>(Xb, Wtb, Hb, INB);
    cudaStreamWaitEvent(sB, evGraph, 0);
    gather_kernel<0><<<GGRID, 256, 0, sB>>>(Hb, b1b, bfx, nullptr);
    prep_wT<<<dim3(HD / 32, 4), 256, 0, sB>>>(W2b_root, W2b_rel, Wt2b, HD);
    gemm_mma<<<ggrid, 256, SMEM_GEMM, sB>>>(bfx, Wt2b, Hb, HD);
    gather_kernel<1><<<GGRID, 256, 0, sB>>>(Hb, b2b, nullptr, bfp);
    cudaEventRecord(evJoin, sB);

    // ---- default: angle chain (critical path) ----
    expand_angle<<<(NN * 72 + T - 1) / T, T>>>(angle);
    cudaStreamWaitEvent(0, evPrepA, 0);
    gemm_mma<<<ggrid, 256, SMEM_GEMM>>>(Xa, Wta, Ha, INA);
    cudaStreamWaitEvent(0, evGraph, 0);
    gather_kernel<0><<<GGRID, 256>>>(Ha, b1a, afx, nullptr);
    cudaStreamWaitEvent(0, evPrep2A, 0);
    gemm_mma<<<ggrid, 256, SMEM_GEMM>>>(afx, Wt2a, Ha, HD);
    gather_kernel<1><<<GGRID, 256>>>(Ha, b2a, nullptr, afp);

    // ---- join + pooling + FC ----
    cudaStreamWaitEvent(0, evJoin, 0);
    pool_kernel<<<(NN + POOL_NODES - 1) / POOL_NODES, 128>>>(crys);
    fc_kernel<<<1, 64>>>(crys, fcW, fcb, out);
}